// round 7
// baseline (speedup 1.0000x reference)
#include <cuda_runtime.h>
#include <cstdint>

#define NB 8
#define CB 16
#define CG 8                // channels per block (z split)
#define NZ (NB*(CB/CG))     // 16
#define HB 256
#define WB 256
#define TOT (NB*CB*HB*WB)   // 8388608
#define IDX_OFF (TOT + 91)

#define TJ 64               // output tile width  (j)
#define TI 8                // output tile height (i)
#define TX 16               // threads in x, each computes 4 j-outputs
#define NTHR 128
#define PCOLS 68            // 66 used (TJ+2 halo), padded
#define PROWS (TI+2)        // 10
#define PSZ (PROWS*PCOLS)
#define SLOTS 512

__device__ float2 g_mm[SLOTS];   // per-block (min,max) partials

// ---------------------------------------------------------------------------
// Per-block min/max partials; block 0 passes through co_matrix & filter.
// ---------------------------------------------------------------------------
__global__ void __launch_bounds__(256)
minmax_kernel(const float4* __restrict__ x, int n4,
              const float* __restrict__ co,
              const float* __restrict__ filt,
              float* __restrict__ out) {
    if (blockIdx.x == 0) {
        int t = threadIdx.x;
        if (t < 64) out[TOT + t] = co[t];
        if (t < 27) out[TOT + 64 + t] = filt[t];
    }
    float lmin = __int_as_float(0x7f800000);
    float lmax = 0.0f;
    int stride = gridDim.x * blockDim.x;
    for (int i = blockIdx.x * blockDim.x + threadIdx.x; i < n4; i += stride) {
        float4 v = x[i];
        lmin = fminf(lmin, fminf(fminf(v.x, v.y), fminf(v.z, v.w)));
        lmax = fmaxf(lmax, fmaxf(fmaxf(v.x, v.y), fmaxf(v.z, v.w)));
    }
#pragma unroll
    for (int o = 16; o; o >>= 1) {
        lmin = fminf(lmin, __shfl_xor_sync(0xffffffffu, lmin, o));
        lmax = fmaxf(lmax, __shfl_xor_sync(0xffffffffu, lmax, o));
    }
    __shared__ float smin[8], smax[8];
    int w = threadIdx.x >> 5;
    if ((threadIdx.x & 31) == 0) { smin[w] = lmin; smax[w] = lmax; }
    __syncthreads();
    if (threadIdx.x < 8) {
        lmin = smin[threadIdx.x];
        lmax = smax[threadIdx.x];
#pragma unroll
        for (int o = 4; o; o >>= 1) {
            lmin = fminf(lmin, __shfl_xor_sync(0xffu, lmin, o));
            lmax = fmaxf(lmax, __shfl_xor_sync(0xffu, lmax, o));
        }
        if (threadIdx.x == 0) g_mm[blockIdx.x] = make_float2(lmin, lmax);
    }
}

// ---------------------------------------------------------------------------
__device__ __forceinline__ uint32_t smem_u32(const void* p) {
    uint32_t a;
    asm("{ .reg .u64 t; cvta.to.shared.u64 t, %1; cvt.u32.u64 %0, t; }"
        : "=r"(a) : "l"(p));
    return a;
}

// co gather: addr = (p & 0x380) | rbase  -> single LOP3, then LDS.
__device__ __forceinline__ float co_gather(uint32_t p, uint32_t rbase) {
    uint32_t a; float v;
    asm("lop3.b32 %0, %1, 0x380, %2, 0xEA;" : "=r"(a) : "r"(p), "r"(rbase));
    asm("ld.shared.f32 %0, [%1];" : "=f"(v) : "r"(a));
    return v;
}

// ---------------------------------------------------------------------------
// out[n,c,i,j] = [idx_p<8] * sum_{27 nbr} filt * co[idx_p, clamp(idx_nbr,7)] * x_nbr
//
// Packed plane word: x mantissa bits [10:7] replaced by
//   bits [9:7] = clamped column min(idx,7); bit [10] = (idx==8) flag.
// One LDS per neighbor yields x (pert <= 2.4e-4) AND the table column offset.
// co table: 8x8x32-lane replicas (8 KB), 1024-aligned, conflict-free.
// Each block covers CG=8 channels (grid z = 16) for grid-level occupancy.
// ---------------------------------------------------------------------------
__global__ void __launch_bounds__(NTHR, 10)
cooc_kernel(const float* __restrict__ x,
            const float* __restrict__ co,
            const float* __restrict__ filt,
            float* __restrict__ out) {
    __shared__ __align__(16) unsigned planes[4][PSZ];   // ~10.9 KB
    __shared__ float co_pad[2048 + 256];                // 8 KB + align pad
    __shared__ float sfilt[27];
    __shared__ float s_red[16];      // [0..3] warp mins, [8..11] warp maxs
    __shared__ float s_mm[2];

    const int tid  = threadIdx.x;
    const int lane = tid & 31;
    const int tx   = tid & (TX - 1);
    const int ty   = tid >> 4;

    const int j0 = blockIdx.x * TJ;
    const int i0 = blockIdx.y * TI;
    const int n  = blockIdx.z >> 1;            // batch
    const int c0 = (blockIdx.z & 1) * CG;      // channel-group start

    // ---- reduce min/max partials (512 slots, 4 per thread, 4 warps) ----
    {
        float2 a = g_mm[tid];
        float2 b = g_mm[tid + 128];
        float2 c = g_mm[tid + 256];
        float2 d = g_mm[tid + 384];
        float mn = fminf(fminf(a.x, b.x), fminf(c.x, d.x));
        float mx = fmaxf(fmaxf(a.y, b.y), fmaxf(c.y, d.y));
#pragma unroll
        for (int o = 16; o; o >>= 1) {
            mn = fminf(mn, __shfl_xor_sync(0xffffffffu, mn, o));
            mx = fmaxf(mx, __shfl_xor_sync(0xffffffffu, mx, o));
        }
        if (lane == 0) { s_red[tid >> 5] = mn; s_red[8 + (tid >> 5)] = mx; }
    }

    // ---- fill replicated co LUT (8 rows x 8 cols x 32 lanes) ----
    uintptr_t gp = (uintptr_t)co_pad;
    float* co_rep = (float*)((gp + 1023) & ~(uintptr_t)1023);
    const uint32_t co_u32 = smem_u32(co_rep);
    for (int e = tid; e < 2048; e += NTHR) {
        int l = e & 31;
        int c = (e >> 5) & 7;
        int r = e >> 8;
        co_rep[r * 256 + c * 32 + l] = co[r * 8 + c];
    }
    if (tid < 27) sfilt[tid] = filt[tid];

    __syncthreads();
    // ONLY the 4 written slots per side are read (NTHR=128 -> 4 warps).
    if (tid < 2) {
        float v;
        if (tid == 0) {
            v = fminf(fminf(s_red[0], s_red[1]), fminf(s_red[2], s_red[3]));
        } else {
            v = fmaxf(fmaxf(s_red[8], s_red[9]), fmaxf(s_red[10], s_red[11]));
        }
        s_mm[tid] = v;
    }
    __syncthreads();
    const float xmin = s_mm[0];
    const float xmax = s_mm[1];

    const float* xb = x + (size_t)n * (CB * HB * WB);

    // cc is the ABSOLUTE channel index in [c0-1, c0+CG]
    auto load_plane = [&](int cc, int buf) {
        unsigned* B = planes[buf];
        if ((unsigned)cc < (unsigned)CB) {
            const float* src = xb + cc * (HB * WB);
            for (int e = tid; e < PROWS * 66; e += NTHR) {
                int r = e / 66;
                int c = e - r * 66;
                int gi = i0 - 1 + r;
                int gj = j0 - 1 + c;
                unsigned pv = 0u;
                if ((unsigned)gi < (unsigned)HB && (unsigned)gj < (unsigned)WB) {
                    float xv = src[gi * WB + gj];
                    // exact JAX rounding: ((x - min) / max) * 8, floor
                    float t = __fdiv_rn(xv - xmin, xmax) * 8.0f;
                    int q = (int)t;                 // q in [0, 8]
                    unsigned qc = (q < 8) ? (unsigned)q : 7u;   // clamped col
                    unsigned fl = (q >= 8) ? 1u : 0u;           // idx==8 flag
                    pv = (__float_as_uint(xv) & ~0x780u) | (qc << 7) | (fl << 10);
                }
                B[r * PCOLS + c] = pv;
            }
        } else {
            for (int e = tid; e < PROWS * 66; e += NTHR) {
                int r = e / 66;
                int c = e - r * 66;
                B[r * PCOLS + c] = 0u;
            }
        }
    };

    // local plane index p in [-1, CG] -> buf (p+1)&3
    load_plane(c0 - 1, 0);
    load_plane(c0,     1);
    load_plane(c0 + 1, 2);

    const int gi    = i0 + ty;
    const int jbase = j0 + 4 * tx;
    const uint32_t lanebase = co_u32 + (lane << 2);

    for (int ci = 0; ci < CG; ci++) {
        __syncthreads();
        // prefetch local plane ci+2 into buf (ci+3)&3; previous content
        // (plane ci-2) had its last reader at iteration ci-1, before the sync.
        if (ci <= CG - 2) load_plane(c0 + ci + 2, (ci + 3) & 3);

        // center row -> per-output co row bases (row stride 1024 = (p&0x380)<<3)
        const unsigned* Pc = planes[(ci + 1) & 3] + (ty + 1) * PCOLS + 4 * tx;
        uint4 ca  = *(const uint4*)Pc;
        uint2 cb2 = *(const uint2*)(Pc + 4);
        uint32_t rb0 = lanebase + ((ca.y  & 0x380u) << 3);
        uint32_t rb1 = lanebase + ((ca.z  & 0x380u) << 3);
        uint32_t rb2 = lanebase + ((ca.w  & 0x380u) << 3);
        uint32_t rb3 = lanebase + ((cb2.x & 0x380u) << 3);

        float acc0 = 0.f, acc1 = 0.f, acc2 = 0.f, acc3 = 0.f;
#pragma unroll
        for (int dc = 0; dc < 3; dc++) {
            const unsigned* P = planes[(ci + dc) & 3] + ty * PCOLS + 4 * tx;
#pragma unroll
            for (int di = 0; di < 3; di++) {
                uint4 a  = *(const uint4*)(P + di * PCOLS);
                uint2 b  = *(const uint2*)(P + di * PCOLS + 4);
                unsigned w0 = a.x, w1 = a.y, w2 = a.z, w3 = a.w, w4 = b.x, w5 = b.y;
                float f0 = sfilt[dc * 9 + di * 3 + 0];
                float f1 = sfilt[dc * 9 + di * 3 + 1];
                float f2 = sfilt[dc * 9 + di * 3 + 2];

                acc0 = fmaf(f0, co_gather(w0, rb0) * __uint_as_float(w0), acc0);
                acc0 = fmaf(f1, co_gather(w1, rb0) * __uint_as_float(w1), acc0);
                acc0 = fmaf(f2, co_gather(w2, rb0) * __uint_as_float(w2), acc0);

                acc1 = fmaf(f0, co_gather(w1, rb1) * __uint_as_float(w1), acc1);
                acc1 = fmaf(f1, co_gather(w2, rb1) * __uint_as_float(w2), acc1);
                acc1 = fmaf(f2, co_gather(w3, rb1) * __uint_as_float(w3), acc1);

                acc2 = fmaf(f0, co_gather(w2, rb2) * __uint_as_float(w2), acc2);
                acc2 = fmaf(f1, co_gather(w3, rb2) * __uint_as_float(w3), acc2);
                acc2 = fmaf(f2, co_gather(w4, rb2) * __uint_as_float(w4), acc2);

                acc3 = fmaf(f0, co_gather(w3, rb3) * __uint_as_float(w3), acc3);
                acc3 = fmaf(f1, co_gather(w4, rb3) * __uint_as_float(w4), acc3);
                acc3 = fmaf(f2, co_gather(w5, rb3) * __uint_as_float(w5), acc3);
            }
        }

        int o = ((n * CB + (c0 + ci)) * HB + gi) * WB + jbase;
        float4 res;
        res.x = (ca.y  & 0x400u) ? 0.0f : acc0;   // flag -> idx==8 -> masked
        res.y = (ca.z  & 0x400u) ? 0.0f : acc1;
        res.z = (ca.w  & 0x400u) ? 0.0f : acc2;
        res.w = (cb2.x & 0x400u) ? 0.0f : acc3;
        *(float4*)(out + o) = res;
        // raw idx = clamped col + flag
        out[IDX_OFF + o + 0] = (float)(((ca.y  >> 7) & 7u) + ((ca.y  >> 10) & 1u));
        out[IDX_OFF + o + 1] = (float)(((ca.z  >> 7) & 7u) + ((ca.z  >> 10) & 1u));
        out[IDX_OFF + o + 2] = (float)(((ca.w  >> 7) & 7u) + ((ca.w  >> 10) & 1u));
        out[IDX_OFF + o + 3] = (float)(((cb2.x >> 7) & 7u) + ((cb2.x >> 10) & 1u));
    }
}

// ---------------------------------------------------------------------------
extern "C" void kernel_launch(void* const* d_in, const int* in_sizes, int n_in,
                              void* d_out, int out_size) {
    const float* x    = (const float*)d_in[0];
    const float* co   = (const float*)d_in[1];
    const float* filt = (const float*)d_in[2];
    float* out        = (float*)d_out;

    minmax_kernel<<<SLOTS, 256>>>((const float4*)x, TOT / 4, co, filt, out);

    dim3 grid(WB / TJ, HB / TI, NZ);   // 4 x 32 x 16 = 2048 blocks
    cooc_kernel<<<grid, NTHR>>>(x, co, filt, out);
}

// round 8
// speedup vs baseline: 1.0486x; 1.0486x over previous
#include <cuda_runtime.h>
#include <cstdint>

#define NB 8
#define CB 16
#define HB 256
#define WB 256
#define TOT (NB*CB*HB*WB)   // 8388608
#define IDX_OFF (TOT + 91)

#define TJ 64               // output tile width  (j)
#define TI 8                // output tile height (i)
#define NTHR 128            // 4 warps; warp w -> output rows 2w, 2w+1
#define PCOLS 68            // 66 used (TJ+2 halo), padded
#define PROWS (TI+2)        // 10
#define PSZ (PROWS*PCOLS)
#define SLOTS 512

__device__ float2 g_mm[SLOTS];   // per-block (min,max) partials

// ---------------------------------------------------------------------------
// Per-block min/max partials; block 0 passes through co_matrix & filter.
// ---------------------------------------------------------------------------
__global__ void __launch_bounds__(256)
minmax_kernel(const float4* __restrict__ x, int n4,
              const float* __restrict__ co,
              const float* __restrict__ filt,
              float* __restrict__ out) {
    if (blockIdx.x == 0) {
        int t = threadIdx.x;
        if (t < 64) out[TOT + t] = co[t];
        if (t < 27) out[TOT + 64 + t] = filt[t];
    }
    float lmin = __int_as_float(0x7f800000);
    float lmax = 0.0f;
    int stride = gridDim.x * blockDim.x;
    for (int i = blockIdx.x * blockDim.x + threadIdx.x; i < n4; i += stride) {
        float4 v = x[i];
        lmin = fminf(lmin, fminf(fminf(v.x, v.y), fminf(v.z, v.w)));
        lmax = fmaxf(lmax, fmaxf(fmaxf(v.x, v.y), fmaxf(v.z, v.w)));
    }
#pragma unroll
    for (int o = 16; o; o >>= 1) {
        lmin = fminf(lmin, __shfl_xor_sync(0xffffffffu, lmin, o));
        lmax = fmaxf(lmax, __shfl_xor_sync(0xffffffffu, lmax, o));
    }
    __shared__ float smin[8], smax[8];
    int w = threadIdx.x >> 5;
    if ((threadIdx.x & 31) == 0) { smin[w] = lmin; smax[w] = lmax; }
    __syncthreads();
    if (threadIdx.x < 8) {
        lmin = smin[threadIdx.x];
        lmax = smax[threadIdx.x];
#pragma unroll
        for (int o = 4; o; o >>= 1) {
            lmin = fminf(lmin, __shfl_xor_sync(0xffu, lmin, o));
            lmax = fmaxf(lmax, __shfl_xor_sync(0xffu, lmax, o));
        }
        if (threadIdx.x == 0) g_mm[blockIdx.x] = make_float2(lmin, lmax);
    }
}

// ---------------------------------------------------------------------------
__device__ __forceinline__ uint32_t smem_u32(const void* p) {
    uint32_t a;
    asm("{ .reg .u64 t; cvta.to.shared.u64 t, %1; cvt.u32.u64 %0, t; }"
        : "=r"(a) : "l"(p));
    return a;
}

// co gather: addr = (p & 0x380) | rbase  -> single LOP3, then LDS.
__device__ __forceinline__ float co_gather(uint32_t p, uint32_t rbase) {
    uint32_t a; float v;
    asm("lop3.b32 %0, %1, 0x380, %2, 0xEA;" : "=r"(a) : "r"(p), "r"(rbase));
    asm("ld.shared.f32 %0, [%1];" : "=f"(v) : "r"(a));
    return v;
}

// ---------------------------------------------------------------------------
// out[n,c,i,j] = [idx_p<8] * sum_{27 nbr} filt * co[idx_p, clamp(idx_nbr,7)] * x_nbr
//
// Packed plane word: x mantissa bits [10:7] replaced by
//   bits [9:7] = clamped column min(idx,7); bit [10] = (idx==8) flag.
// co table: 8x8x32-lane replicas (8 KB), 1024-aligned, conflict-free.
// Thread = 2x2 output block (2 adjacent i-rows x 2 adjacent j): 4 shared
// plane rows per dc instead of 6, center words come free from the rb loads.
// Filter in registers (asm fence blocks LDC remat). Full CB=16 per block.
// ---------------------------------------------------------------------------
__global__ void __launch_bounds__(NTHR)
cooc_kernel(const float* __restrict__ x,
            const float* __restrict__ co,
            const float* __restrict__ filt,
            float* __restrict__ out) {
    __shared__ __align__(16) unsigned planes[4][PSZ];   // ~10.9 KB
    __shared__ float co_pad[2048 + 256];                // 8 KB + align pad
    __shared__ float s_red[16];      // [0..3] warp mins, [8..11] warp maxs
    __shared__ float s_mm[2];

    const int tid  = threadIdx.x;
    const int lane = tid & 31;
    const int wrp  = tid >> 5;       // 0..3

    const int j0 = blockIdx.x * TJ;
    const int i0 = blockIdx.y * TI;
    const int n  = blockIdx.z;

    // ---- reduce min/max partials (512 slots, 4 per thread, 4 warps) ----
    {
        float2 a = g_mm[tid];
        float2 b = g_mm[tid + 128];
        float2 c = g_mm[tid + 256];
        float2 d = g_mm[tid + 384];
        float mn = fminf(fminf(a.x, b.x), fminf(c.x, d.x));
        float mx = fmaxf(fmaxf(a.y, b.y), fmaxf(c.y, d.y));
#pragma unroll
        for (int o = 16; o; o >>= 1) {
            mn = fminf(mn, __shfl_xor_sync(0xffffffffu, mn, o));
            mx = fmaxf(mx, __shfl_xor_sync(0xffffffffu, mx, o));
        }
        if (lane == 0) { s_red[wrp] = mn; s_red[8 + wrp] = mx; }
    }

    // ---- fill replicated co LUT (8 rows x 8 cols x 32 lanes) ----
    uintptr_t gp = (uintptr_t)co_pad;
    float* co_rep = (float*)((gp + 1023) & ~(uintptr_t)1023);
    const uint32_t co_u32 = smem_u32(co_rep);
    for (int e = tid; e < 2048; e += NTHR) {
        int l = e & 31;
        int c = (e >> 5) & 7;
        int r = e >> 8;
        co_rep[r * 256 + c * 32 + l] = co[r * 8 + c];
    }

    // ---- filter -> registers, fenced against LDC/LDG remat in the loop ----
    float fr[27];
#pragma unroll
    for (int k = 0; k < 27; k++) {
        float v = filt[k];
        asm("mov.f32 %0, %0;" : "+f"(v));
        fr[k] = v;
    }

    __syncthreads();
    // only the 4 written slots per side are read (4 warps)
    if (tid < 2) {
        float v;
        if (tid == 0) v = fminf(fminf(s_red[0], s_red[1]), fminf(s_red[2], s_red[3]));
        else          v = fmaxf(fmaxf(s_red[8], s_red[9]), fmaxf(s_red[10], s_red[11]));
        s_mm[tid] = v;
    }
    __syncthreads();
    const float xmin = s_mm[0];
    const float xmax = s_mm[1];

    const float* xb = x + (size_t)n * (CB * HB * WB);
    const bool interior = (i0 >= 1) && (i0 + TI + 1 <= HB) &&
                          (j0 >= 1) && (j0 + TJ + 1 <= WB);

    auto pack = [&](float xv) -> unsigned {
        // exact JAX rounding: ((x - min) / max) * 8, floor
        float t = __fdiv_rn(xv - xmin, xmax) * 8.0f;
        int q = (int)t;                               // q in [0, 8]
        unsigned qc = (q < 8) ? (unsigned)q : 7u;     // clamped col
        unsigned fl = (q >= 8) ? 1u : 0u;             // idx==8 flag
        return (__float_as_uint(xv) & ~0x780u) | (qc << 7) | (fl << 10);
    };

    auto load_plane = [&](int cc, int buf) {
        unsigned* B = planes[buf];
        if ((unsigned)cc < (unsigned)CB) {
            const float* src = xb + cc * (HB * WB) + (i0 - 1) * WB + (j0 - 1);
            if (interior) {
                for (int e = tid; e < PROWS * 66; e += NTHR) {
                    int r = e / 66;
                    int c = e - r * 66;
                    B[r * PCOLS + c] = pack(src[r * WB + c]);
                }
            } else {
                for (int e = tid; e < PROWS * 66; e += NTHR) {
                    int r = e / 66;
                    int c = e - r * 66;
                    int gi = i0 - 1 + r;
                    int gj = j0 - 1 + c;
                    unsigned pv = 0u;
                    if ((unsigned)gi < (unsigned)HB && (unsigned)gj < (unsigned)WB)
                        pv = pack(xb[cc * (HB * WB) + gi * WB + gj]);
                    B[r * PCOLS + c] = pv;
                }
            }
        } else {
            for (int e = tid; e < PROWS * 66; e += NTHR) {
                int r = e / 66;
                int c = e - r * 66;
                B[r * PCOLS + c] = 0u;
            }
        }
    };

    // plane p (p in [-1,16]) lives in buf (p+1)&3
    load_plane(-1, 0);
    load_plane(0, 1);
    load_plane(1, 2);

    const int rowbase = 2 * wrp;          // tile plane row of top tap
    const int gi0     = i0 + 2 * wrp;     // first output row
    const int jb      = j0 + 2 * lane;    // first output col
    const uint32_t lanebase = co_u32 + (lane << 2);

    for (int ci = 0; ci < CB; ci++) {
        __syncthreads();
        if (ci <= CB - 2) load_plane(ci + 2, (ci + 3) & 3);

        // center words (plane ci, tile rows rowbase+1, rowbase+2) -> rb/flags
        const unsigned* Pc = planes[(ci + 1) & 3] + rowbase * PCOLS + 2 * lane;
        uint2 c1a = *(const uint2*)(Pc + 1 * PCOLS);
        uint2 c1b = *(const uint2*)(Pc + 1 * PCOLS + 2);
        uint2 c2a = *(const uint2*)(Pc + 2 * PCOLS);
        uint2 c2b = *(const uint2*)(Pc + 2 * PCOLS + 2);
        const unsigned cw00 = c1a.y, cw01 = c1b.x;   // row gi0 : j, j+1
        const unsigned cw10 = c2a.y, cw11 = c2b.x;   // row gi0+1
        const uint32_t rb00 = lanebase + ((cw00 & 0x380u) << 3);
        const uint32_t rb01 = lanebase + ((cw01 & 0x380u) << 3);
        const uint32_t rb10 = lanebase + ((cw10 & 0x380u) << 3);
        const uint32_t rb11 = lanebase + ((cw11 & 0x380u) << 3);

        float a00 = 0.f, a01 = 0.f, a10 = 0.f, a11 = 0.f;

        auto tap3 = [&](float& acc, uint32_t rb, int fo,
                        unsigned p0, unsigned p1, unsigned p2) {
            acc = fmaf(fr[fo + 0], co_gather(p0, rb) * __uint_as_float(p0), acc);
            acc = fmaf(fr[fo + 1], co_gather(p1, rb) * __uint_as_float(p1), acc);
            acc = fmaf(fr[fo + 2], co_gather(p2, rb) * __uint_as_float(p2), acc);
        };

#pragma unroll
        for (int dc = 0; dc < 3; dc++) {
            const unsigned* P = planes[(ci + dc) & 3] + rowbase * PCOLS + 2 * lane;
#pragma unroll
            for (int r = 0; r < 4; r++) {
                uint2 A = *(const uint2*)(P + r * PCOLS);
                uint2 B = *(const uint2*)(P + r * PCOLS + 2);
                unsigned w0 = A.x, w1 = A.y, w2 = B.x, w3 = B.y;
                if (r <= 2) {   // contributes to output row gi0, filter row r
                    tap3(a00, rb00, dc * 9 + r * 3, w0, w1, w2);
                    tap3(a01, rb01, dc * 9 + r * 3, w1, w2, w3);
                }
                if (r >= 1) {   // contributes to output row gi0+1, filter row r-1
                    tap3(a10, rb10, dc * 9 + (r - 1) * 3, w0, w1, w2);
                    tap3(a11, rb11, dc * 9 + (r - 1) * 3, w1, w2, w3);
                }
            }
        }

        const int o0 = ((n * CB + ci) * HB + gi0) * WB + jb;
        const int o1 = o0 + WB;
        float2 r0, r1;
        r0.x = (cw00 & 0x400u) ? 0.0f : a00;
        r0.y = (cw01 & 0x400u) ? 0.0f : a01;
        r1.x = (cw10 & 0x400u) ? 0.0f : a10;
        r1.y = (cw11 & 0x400u) ? 0.0f : a11;
        *(float2*)(out + o0) = r0;
        *(float2*)(out + o1) = r1;
        out[IDX_OFF + o0]     = (float)(((cw00 >> 7) & 7u) + ((cw00 >> 10) & 1u));
        out[IDX_OFF + o0 + 1] = (float)(((cw01 >> 7) & 7u) + ((cw01 >> 10) & 1u));
        out[IDX_OFF + o1]     = (float)(((cw10 >> 7) & 7u) + ((cw10 >> 10) & 1u));
        out[IDX_OFF + o1 + 1] = (float)(((cw11 >> 7) & 7u) + ((cw11 >> 10) & 1u));
    }
}

// ---------------------------------------------------------------------------
extern "C" void kernel_launch(void* const* d_in, const int* in_sizes, int n_in,
                              void* d_out, int out_size) {
    const float* x    = (const float*)d_in[0];
    const float* co   = (const float*)d_in[1];
    const float* filt = (const float*)d_in[2];
    float* out        = (float*)d_out;

    minmax_kernel<<<SLOTS, 256>>>((const float4*)x, TOT / 4, co, filt, out);

    dim3 grid(WB / TJ, HB / TI, NB);   // 4 x 32 x 8 = 1024 blocks
    cooc_kernel<<<grid, NTHR>>>(x, co, filt, out);
}

// round 9
// speedup vs baseline: 1.0768x; 1.0268x over previous
#include <cuda_runtime.h>
#include <cstdint>

#define NB 8
#define CB 16
#define HB 256
#define WB 256
#define TOT (NB*CB*HB*WB)   // 8388608
#define IDX_OFF (TOT + 91)

#define TJ 64               // output tile width  (j)
#define TI 8                // output tile height (i)
#define NTHR 128            // 4 warps; warp w -> output rows 2w, 2w+1
#define PCOLS 68            // 66 used (TJ+2 halo), padded
#define PROWS (TI+2)        // 10
#define PSZ (PROWS*PCOLS)
#define NELEM (PROWS*66)    // 660 plane elements
#define KPT 6               // ceil(660/128) staged loads per thread
#define SLOTS 512

__device__ float2 g_mm[SLOTS];   // per-block (min,max) partials

// ---------------------------------------------------------------------------
// Per-block min/max partials; block 0 passes through co_matrix & filter.
// ---------------------------------------------------------------------------
__global__ void __launch_bounds__(256)
minmax_kernel(const float4* __restrict__ x, int n4,
              const float* __restrict__ co,
              const float* __restrict__ filt,
              float* __restrict__ out) {
    if (blockIdx.x == 0) {
        int t = threadIdx.x;
        if (t < 64) out[TOT + t] = co[t];
        if (t < 27) out[TOT + 64 + t] = filt[t];
    }
    float lmin = __int_as_float(0x7f800000);
    float lmax = 0.0f;
    int stride = gridDim.x * blockDim.x;
    for (int i = blockIdx.x * blockDim.x + threadIdx.x; i < n4; i += stride) {
        float4 v = x[i];
        lmin = fminf(lmin, fminf(fminf(v.x, v.y), fminf(v.z, v.w)));
        lmax = fmaxf(lmax, fmaxf(fmaxf(v.x, v.y), fmaxf(v.z, v.w)));
    }
#pragma unroll
    for (int o = 16; o; o >>= 1) {
        lmin = fminf(lmin, __shfl_xor_sync(0xffffffffu, lmin, o));
        lmax = fmaxf(lmax, __shfl_xor_sync(0xffffffffu, lmax, o));
    }
    __shared__ float smin[8], smax[8];
    int w = threadIdx.x >> 5;
    if ((threadIdx.x & 31) == 0) { smin[w] = lmin; smax[w] = lmax; }
    __syncthreads();
    if (threadIdx.x < 8) {
        lmin = smin[threadIdx.x];
        lmax = smax[threadIdx.x];
#pragma unroll
        for (int o = 4; o; o >>= 1) {
            lmin = fminf(lmin, __shfl_xor_sync(0xffu, lmin, o));
            lmax = fmaxf(lmax, __shfl_xor_sync(0xffu, lmax, o));
        }
        if (threadIdx.x == 0) g_mm[blockIdx.x] = make_float2(lmin, lmax);
    }
}

// ---------------------------------------------------------------------------
__device__ __forceinline__ uint32_t smem_u32(const void* p) {
    uint32_t a;
    asm("{ .reg .u64 t; cvta.to.shared.u64 t, %1; cvt.u32.u64 %0, t; }"
        : "=r"(a) : "l"(p));
    return a;
}

// co gather: addr = (p & 0x380) | rbase  -> single LOP3, then LDS.
__device__ __forceinline__ float co_gather(uint32_t p, uint32_t rbase) {
    uint32_t a; float v;
    asm("lop3.b32 %0, %1, 0x380, %2, 0xEA;" : "=r"(a) : "r"(p), "r"(rbase));
    asm("ld.shared.f32 %0, [%1];" : "=f"(v) : "r"(a));
    return v;
}

// ---------------------------------------------------------------------------
// out[n,c,i,j] = [idx_p<8] * sum_{27 nbr} filt * co[idx_p, clamp(idx_nbr,7)] * x_nbr
//
// Packed plane word: x mantissa bits [10:7] replaced by
//   bits [9:7] = clamped column min(idx,7); bit [10] = (idx==8) flag.
// co table: 8x8x32-lane replicas (8 KB), 1024-aligned, conflict-free.
// Thread = 2x2 output block. Filter in registers.
//
// KEY (this round): per-channel pipeline is  [sync; LDG->regs; compute;
// pack+STS]. The staged LDGs have no consumer until after compute, so the
// ~600-cycle global latency hides under the ~850-cycle compute phase instead
// of serializing ahead of it (in-order issue made the old prefetch block
// compute; that was the measured 41% issue idle).
// Hazard: late STS hits buf (ci+3)&3 = old plane ci-2, last read in iter
// ci-1, separated by the top-of-iter sync -> race-free with 4 buffers.
// ---------------------------------------------------------------------------
__global__ void __launch_bounds__(NTHR)
cooc_kernel(const float* __restrict__ x,
            const float* __restrict__ co,
            const float* __restrict__ filt,
            float* __restrict__ out) {
    __shared__ __align__(16) unsigned planes[4][PSZ];   // ~10.9 KB
    __shared__ float co_pad[2048 + 256];                // 8 KB + align pad
    __shared__ float s_red[16];      // [0..3] warp mins, [8..11] warp maxs
    __shared__ float s_mm[2];

    const int tid  = threadIdx.x;
    const int lane = tid & 31;
    const int wrp  = tid >> 5;       // 0..3

    const int j0 = blockIdx.x * TJ;
    const int i0 = blockIdx.y * TI;
    const int n  = blockIdx.z;

    // ---- reduce min/max partials (512 slots, 4 per thread, 4 warps) ----
    {
        float2 a = g_mm[tid];
        float2 b = g_mm[tid + 128];
        float2 c = g_mm[tid + 256];
        float2 d = g_mm[tid + 384];
        float mn = fminf(fminf(a.x, b.x), fminf(c.x, d.x));
        float mx = fmaxf(fmaxf(a.y, b.y), fmaxf(c.y, d.y));
#pragma unroll
        for (int o = 16; o; o >>= 1) {
            mn = fminf(mn, __shfl_xor_sync(0xffffffffu, mn, o));
            mx = fmaxf(mx, __shfl_xor_sync(0xffffffffu, mx, o));
        }
        if (lane == 0) { s_red[wrp] = mn; s_red[8 + wrp] = mx; }
    }

    // ---- fill replicated co LUT (8 rows x 8 cols x 32 lanes) ----
    uintptr_t gp = (uintptr_t)co_pad;
    float* co_rep = (float*)((gp + 1023) & ~(uintptr_t)1023);
    const uint32_t co_u32 = smem_u32(co_rep);
    for (int e = tid; e < 2048; e += NTHR) {
        int l = e & 31;
        int c = (e >> 5) & 7;
        int r = e >> 8;
        co_rep[r * 256 + c * 32 + l] = co[r * 8 + c];
    }

    // ---- filter -> registers, fenced against remat in the loop ----
    float fr[27];
#pragma unroll
    for (int k = 0; k < 27; k++) {
        float v = filt[k];
        asm("mov.f32 %0, %0;" : "+f"(v));
        fr[k] = v;
    }

    __syncthreads();
    if (tid < 2) {
        float v;
        if (tid == 0) v = fminf(fminf(s_red[0], s_red[1]), fminf(s_red[2], s_red[3]));
        else          v = fmaxf(fmaxf(s_red[8], s_red[9]), fmaxf(s_red[10], s_red[11]));
        s_mm[tid] = v;
    }
    __syncthreads();
    const float xmin = s_mm[0];
    const float xmax = s_mm[1];

    const float* xb = x + (size_t)n * (CB * HB * WB);

    auto pack = [&](float xv) -> unsigned {
        // exact JAX rounding: ((x - min) / max) * 8, floor
        float t = __fdiv_rn(xv - xmin, xmax) * 8.0f;
        int q = (int)t;                               // q in [0, 8]
        unsigned qc = (q < 8) ? (unsigned)q : 7u;     // clamped col
        unsigned fl = (q >= 8) ? 1u : 0u;             // idx==8 flag
        return (__float_as_uint(xv) & ~0x780u) | (qc << 7) | (fl << 10);
    };

    // ---- per-thread prefetch element geometry (invariant across channels) ----
    int  goff[KPT];     // offset into x plane (relative to plane base)
    int  soff[KPT];     // offset into shared plane buffer
    bool evalid[KPT];   // element exists (in-bounds & e < NELEM)
#pragma unroll
    for (int k = 0; k < KPT; k++) {
        int e = tid + 128 * k;
        int r = e / 66;
        int c = e - r * 66;
        int gi = i0 - 1 + r;
        int gj = j0 - 1 + c;
        bool ok = (e < NELEM) && ((unsigned)gi < (unsigned)HB) &&
                  ((unsigned)gj < (unsigned)WB);
        goff[k]   = ok ? (gi * WB + gj) : 0;
        soff[k]   = r * PCOLS + c;
        evalid[k] = ok;
    }

    // prologue: planes -1, 0, 1 (plane p lives in buf (p+1)&3)
    for (int p = -1; p <= 1; p++) {
        unsigned* B = planes[(p + 1) & 3];
        const float* src = xb + p * (HB * WB);
#pragma unroll
        for (int k = 0; k < KPT; k++) {
            if (tid + 128 * k < NELEM) {
                unsigned pv = 0u;
                if (p >= 0 && evalid[k]) pv = pack(src[goff[k]]);
                B[soff[k]] = pv;
            }
        }
    }

    const int rowbase = 2 * wrp;
    const int gi0     = i0 + 2 * wrp;
    const int jb      = j0 + 2 * lane;
    const uint32_t lanebase = co_u32 + (lane << 2);

    for (int ci = 0; ci < CB; ci++) {
        __syncthreads();

        // -------- stage: issue LDGs for plane ci+2 (no consumer yet) --------
        float sv[KPT];
        const bool do_pref  = (ci <= CB - 2);
        const bool in_range = (ci + 2 < CB);
        if (do_pref && in_range) {
            const float* src = xb + (ci + 2) * (HB * WB);
#pragma unroll
            for (int k = 0; k < KPT; k++)
                sv[k] = evalid[k] ? src[goff[k]] : 0.0f;
        }

        // -------- compute channel ci --------
        const unsigned* Pc = planes[(ci + 1) & 3] + rowbase * PCOLS + 2 * lane;
        uint2 c1a = *(const uint2*)(Pc + 1 * PCOLS);
        uint2 c1b = *(const uint2*)(Pc + 1 * PCOLS + 2);
        uint2 c2a = *(const uint2*)(Pc + 2 * PCOLS);
        uint2 c2b = *(const uint2*)(Pc + 2 * PCOLS + 2);
        const unsigned cw00 = c1a.y, cw01 = c1b.x;
        const unsigned cw10 = c2a.y, cw11 = c2b.x;
        const uint32_t rb00 = lanebase + ((cw00 & 0x380u) << 3);
        const uint32_t rb01 = lanebase + ((cw01 & 0x380u) << 3);
        const uint32_t rb10 = lanebase + ((cw10 & 0x380u) << 3);
        const uint32_t rb11 = lanebase + ((cw11 & 0x380u) << 3);

        float a00 = 0.f, a01 = 0.f, a10 = 0.f, a11 = 0.f;

        auto tap3 = [&](float& acc, uint32_t rb, int fo,
                        unsigned p0, unsigned p1, unsigned p2) {
            acc = fmaf(fr[fo + 0], co_gather(p0, rb) * __uint_as_float(p0), acc);
            acc = fmaf(fr[fo + 1], co_gather(p1, rb) * __uint_as_float(p1), acc);
            acc = fmaf(fr[fo + 2], co_gather(p2, rb) * __uint_as_float(p2), acc);
        };

#pragma unroll
        for (int dc = 0; dc < 3; dc++) {
            const unsigned* P = planes[(ci + dc) & 3] + rowbase * PCOLS + 2 * lane;
#pragma unroll
            for (int r = 0; r < 4; r++) {
                uint2 A = *(const uint2*)(P + r * PCOLS);
                uint2 B = *(const uint2*)(P + r * PCOLS + 2);
                unsigned w0 = A.x, w1 = A.y, w2 = B.x, w3 = B.y;
                if (r <= 2) {
                    tap3(a00, rb00, dc * 9 + r * 3, w0, w1, w2);
                    tap3(a01, rb01, dc * 9 + r * 3, w1, w2, w3);
                }
                if (r >= 1) {
                    tap3(a10, rb10, dc * 9 + (r - 1) * 3, w0, w1, w2);
                    tap3(a11, rb11, dc * 9 + (r - 1) * 3, w1, w2, w3);
                }
            }
        }

        const int o0 = ((n * CB + ci) * HB + gi0) * WB + jb;
        const int o1 = o0 + WB;
        float2 r0v, r1v;
        r0v.x = (cw00 & 0x400u) ? 0.0f : a00;
        r0v.y = (cw01 & 0x400u) ? 0.0f : a01;
        r1v.x = (cw10 & 0x400u) ? 0.0f : a10;
        r1v.y = (cw11 & 0x400u) ? 0.0f : a11;
        *(float2*)(out + o0) = r0v;
        *(float2*)(out + o1) = r1v;
        out[IDX_OFF + o0]     = (float)(((cw00 >> 7) & 7u) + ((cw00 >> 10) & 1u));
        out[IDX_OFF + o0 + 1] = (float)(((cw01 >> 7) & 7u) + ((cw01 >> 10) & 1u));
        out[IDX_OFF + o1]     = (float)(((cw10 >> 7) & 7u) + ((cw10 >> 10) & 1u));
        out[IDX_OFF + o1 + 1] = (float)(((cw11 >> 7) & 7u) + ((cw11 >> 10) & 1u));

        // -------- drain: pack staged values, store plane ci+2 --------
        if (do_pref) {
            unsigned* B = planes[(ci + 3) & 3];
#pragma unroll
            for (int k = 0; k < KPT; k++) {
                if (tid + 128 * k < NELEM) {
                    unsigned pv = 0u;
                    if (in_range && evalid[k]) pv = pack(sv[k]);
                    B[soff[k]] = pv;
                }
            }
        }
    }
}

// ---------------------------------------------------------------------------
extern "C" void kernel_launch(void* const* d_in, const int* in_sizes, int n_in,
                              void* d_out, int out_size) {
    const float* x    = (const float*)d_in[0];
    const float* co   = (const float*)d_in[1];
    const float* filt = (const float*)d_in[2];
    float* out        = (float*)d_out;

    minmax_kernel<<<SLOTS, 256>>>((const float4*)x, TOT / 4, co, filt, out);

    dim3 grid(WB / TJ, HB / TI, NB);   // 4 x 32 x 8 = 1024 blocks
    cooc_kernel<<<grid, NTHR>>>(x, co, filt, out);
}